// round 5
// baseline (speedup 1.0000x reference)
#include <cuda_runtime.h>

#define BB 4
#define CC 64
#define HH 192
#define WWI 192
#define HWSZ (HH*WWI)
#define HD 96
#define WD 96

// ---- scratch (static device globals; no runtime allocation) ----
__device__ float g_down[BB*CC*HD*WD];          // 9.4 MB
__device__ float g_df[BB*HWSZ];
__device__ float g_nsq[BB*HWSZ];
__device__ unsigned g_dfmin[BB];
__device__ unsigned g_dfmax[BB];
__device__ float g_sum[BB*CC];
__device__ float g_ssq[BB*CC];

// GEMM1 weights + biases on the constant port (off the smem crossbar)
__constant__ float cW1[128*64];   // 32 KB
__constant__ float cB1[128];
__constant__ float cB2[64];

typedef unsigned long long ull;

__device__ __forceinline__ ull pack2(float lo, float hi) {
    ull r; asm("mov.b64 %0, {%1, %2};" : "=l"(r) : "f"(lo), "f"(hi)); return r;
}
__device__ __forceinline__ void unpack2(ull v, float& lo, float& hi) {
    asm("mov.b64 {%0, %1}, %2;" : "=f"(lo), "=f"(hi) : "l"(v));
}
__device__ __forceinline__ ull fma2(ull a, ull b, ull c) {
    ull d; asm("fma.rn.f32x2 %0, %1, %2, %3;" : "=l"(d) : "l"(a), "l"(b), "l"(c)); return d;
}
__device__ __forceinline__ ull add2(ull a, ull b) {
    ull d; asm("add.rn.f32x2 %0, %1, %2;" : "=l"(d) : "l"(a), "l"(b)); return d;
}

__global__ void k_init() {
    int t = blockIdx.x * 256 + threadIdx.x;
    if (t < BB) { g_dfmin[t] = 0x7f800000u; g_dfmax[t] = 0u; }
    if (t < BB*CC) { g_sum[t] = 0.f; g_ssq[t] = 0.f; }
}

// 0.5x bilinear == 2x2 average pooling; also accumulates GroupNorm sum/sumsq.
__global__ void k_down(const float* __restrict__ x) {
    int blk  = blockIdx.x;
    int bc   = blk >> 1;
    int half = blk & 1;
    const float* xp = x + (size_t)bc * HWSZ;
    float* dp = g_down + (size_t)bc * (HD*WD);

    float s = 0.f, q = 0.f;
    for (int idx = threadIdx.x; idx < 48*48; idx += 256) {
        int jp = idx % 48;
        int r  = idx / 48;
        int ii = half * 48 + r;
        const float4 v0 = *(const float4*)(xp + (2*ii)   * WWI + 4*jp);
        const float4 v1 = *(const float4*)(xp + (2*ii+1) * WWI + 4*jp);
        float o0 = 0.5f*(0.5f*v0.x + 0.5f*v1.x) + 0.5f*(0.5f*v0.y + 0.5f*v1.y);
        float o1 = 0.5f*(0.5f*v0.z + 0.5f*v1.z) + 0.5f*(0.5f*v0.w + 0.5f*v1.w);
        dp[ii*WD + 2*jp]   = o0;
        dp[ii*WD + 2*jp+1] = o1;
        s += ((v0.x+v0.y)+(v0.z+v0.w)) + ((v1.x+v1.y)+(v1.z+v1.w));
        q += ((v0.x*v0.x+v0.y*v0.y)+(v0.z*v0.z+v0.w*v0.w))
           + ((v1.x*v1.x+v1.y*v1.y)+(v1.z*v1.z+v1.w*v1.w));
    }
    __shared__ float ss[256], sq[256];
    ss[threadIdx.x] = s; sq[threadIdx.x] = q;
    __syncthreads();
    for (int st = 128; st > 0; st >>= 1) {
        if (threadIdx.x < st) {
            ss[threadIdx.x] += ss[threadIdx.x+st];
            sq[threadIdx.x] += sq[threadIdx.x+st];
        }
        __syncthreads();
    }
    if (threadIdx.x == 0) {
        atomicAdd(&g_sum[bc], ss[0]);
        atomicAdd(&g_ssq[bc], sq[0]);
    }
}

// df map (sum_c |x - up(down(x))|), per-pixel normsq over C, per-batch min/max
__global__ void k_df(const float* __restrict__ x) {
    int p = blockIdx.x * 256 + threadIdx.x;
    int b = blockIdx.y;
    int h = p / WWI, w = p % WWI;

    float sh = fminf(fmaxf((h + 0.5f) * 0.5f - 0.5f, 0.f), (float)(HD-1));
    float sw = fminf(fmaxf((w + 0.5f) * 0.5f - 0.5f, 0.f), (float)(WD-1));
    int hl = (int)sh; int hh2 = min(hl+1, HD-1); float wh = sh - (float)hl;
    int wl = (int)sw; int wh2 = min(wl+1, WD-1); float ww = sw - (float)wl;
    int i00 = hl*WD+wl, i10 = hh2*WD+wl, i01 = hl*WD+wh2, i11 = hh2*WD+wh2;

    const float* xb = x + (size_t)b * CC * HWSZ + p;
    const float* db = g_down + (size_t)b * CC * HD * WD;

    float df = 0.f, nsq = 0.f;
    #pragma unroll 8
    for (int c = 0; c < CC; c++) {
        float xv = xb[(size_t)c * HWSZ];
        const float* dc = db + c * HD * WD;
        float u0  = dc[i00]*(1.f-wh) + dc[i10]*wh;
        float u1  = dc[i01]*(1.f-wh) + dc[i11]*wh;
        float xdu = u0*(1.f-ww) + u1*ww;
        df  += fabsf(xv - xdu);
        nsq += xv * xv;
    }
    g_df[b*HWSZ+p]  = df;
    g_nsq[b*HWSZ+p] = nsq;

    __shared__ float smn[256], smx[256];
    int tid = threadIdx.x;
    smn[tid] = df; smx[tid] = df;
    __syncthreads();
    for (int s = 128; s > 0; s >>= 1) {
        if (tid < s) {
            smn[tid] = fminf(smn[tid], smn[tid+s]);
            smx[tid] = fmaxf(smx[tid], smx[tid+s]);
        }
        __syncthreads();
    }
    if (tid == 0) {
        atomicMin(&g_dfmin[b], __float_as_uint(smn[0]));
        atomicMax(&g_dfmax[b], __float_as_uint(smx[0]));
    }
}

// Fused everything-else. TWO THREADS PER PIXEL (lanes L and L^16), 32 channels each.
// smem (floats): sW2t[8192] | sA[64] | sB[64]
__global__ void __launch_bounds__(128) k_mainffn(
    const float* __restrict__ x,
    const float* __restrict__ gw, const float* __restrict__ gb,
    const float* __restrict__ w2,
    float* __restrict__ out)
{
    extern __shared__ float sm[];
    float* sW2t = sm;
    float* sA   = sm + 8192;
    float* sB   = sm + 8256;
    int tid = threadIdx.x;
    int wid  = tid >> 5;
    int lane = tid & 31;
    int sub  = lane & 15;
    int half = lane >> 4;
    int c0   = half * 32;          // this thread's channel base

    // block handles 64 consecutive pixels; b is uniform per block (HWSZ % 64 == 0)
    int n = blockIdx.x * 64 + wid * 16 + sub;
    int b = n / HWSZ;
    int p = n - b * HWSZ;

    for (int i = tid; i < 8192; i += 128) {
        int o = i >> 6, c = i & 63;
        sW2t[i] = w2[c * 128 + o];
    }
    if (tid < 64) {                // GroupNorm affine fold, per block (cheap)
        int c = tid, g = c >> 1;
        int base = b * CC + 2 * g;
        float n2  = 2.f * (float)HWSZ;
        float mu  = (g_sum[base] + g_sum[base+1]) / n2;
        float var = (g_ssq[base] + g_ssq[base+1]) / n2 - mu*mu;
        float inv = rsqrtf(var + 1e-5f);
        float A = gw[c] * inv;
        sA[c] = A;
        sB[c] = gb[c] - mu * A;
    }
    __syncthreads();

    // ---------------- phase A: enhanced for OWN 32 channels ----------------
    int h = p / WWI, w = p % WWI;
    const float* xb = x + (size_t)b * CC * HWSZ + (size_t)c0 * HWSZ + p;

    float dmin = __uint_as_float(g_dfmin[b]);
    float dmax = __uint_as_float(g_dfmax[b]);
    float df   = g_df[b*HWSZ + p];
    float t0   = (df - dmin) / ((dmax - dmin) + 1e-8f);
    float dfp  = t0 * t0;

    float e[32];

    if (!(dfp > 0.3f)) {   // not processed: enhanced = x + (A*x+B)
        #pragma unroll
        for (int c = 0; c < 32; c++) {
            float xv = xb[(size_t)c * HWSZ];
            e[c] = xv + (sA[c0+c]*xv + sB[c0+c]);
        }
    } else {
        unsigned pmask = (1u << lane) | (1u << (lane ^ 16));   // pair never diverges
        int kk = min(1 + (int)rintf(dfp * 15.f), 9);

        bool val[9];
        int  doff[9];
        #pragma unroll
        for (int j = 0; j < 9; j++) {
            int dy = j/3 - 1, dx = j - 3*(j/3) - 1;
            val[j]  = ((unsigned)(h+dy) < HH) && ((unsigned)(w+dx) < WWI);
            doff[j] = dy * WWI + dx;
        }

        float dot[9];
        #pragma unroll
        for (int j = 0; j < 9; j++) dot[j] = 0.f;

        #pragma unroll 4
        for (int c = 0; c < 32; c++) {
            const float* rc = xb + (size_t)c * HWSZ;
            float xv = rc[0];
            #pragma unroll
            for (int j = 0; j < 9; j++)
                if (val[j]) dot[j] = fmaf(xv, rc[doff[j]], dot[j]);
        }
        #pragma unroll
        for (int j = 0; j < 9; j++)
            dot[j] += __shfl_xor_sync(pmask, dot[j], 16);   // full-C dot

        float ncen = fmaxf(sqrtf(g_nsq[b*HWSZ + p]), 1e-12f);
        float sim[9];
        #pragma unroll
        for (int j = 0; j < 9; j++) {
            if (val[j]) {
                float nn = fmaxf(sqrtf(g_nsq[b*HWSZ + p + doff[j]]), 1e-12f);
                sim[j] = dot[j] / (ncen * nn);
            } else {
                sim[j] = 0.f;
            }
        }

        // stable top-k via rank (== stable argsort of -sim), in registers
        float wt[9];
        float wsum = 0.f;
        #pragma unroll
        for (int j = 0; j < 9; j++) {
            int rank = 0;
            #pragma unroll
            for (int l = 0; l < 9; l++) {
                if (l != j) {
                    bool beats = (sim[l] > sim[j]) || (sim[l] == sim[j] && l < j);
                    rank += beats ? 1 : 0;
                }
            }
            float wv = (rank < kk) ? expf(sim[j]) : 0.f;
            wt[j] = wv;
            wsum += wv;
        }
        float invw = 1.f / fmaxf(wsum, 1e-12f);
        #pragma unroll
        for (int j = 0; j < 9; j++) wt[j] *= invw;

        #pragma unroll 4
        for (int c = 0; c < 32; c++) {
            const float* rc = xb + (size_t)c * HWSZ;
            float acc = 0.f;
            #pragma unroll
            for (int j = 0; j < 9; j++)
                if (val[j]) acc = fmaf(wt[j], rc[doff[j]], acc);
            float xv = rc[0];
            e[c] = acc + (sA[c0+c]*xv + sB[c0+c]);
        }
    }

    // ---------------- phase B: FFN, pair-split (32 channels per thread) ----------------
    ull E2[16], acc2[16];
    #pragma unroll
    for (int q = 0; q < 16; q++) {
        E2[q]   = pack2(e[2*q], e[2*q+1]);
        acc2[q] = add2(E2[q], pack2(cB2[c0+2*q], cB2[c0+2*q+1]));   // enhanced + b2
    }

    #pragma unroll 2
    for (int o = 0; o < 128; o++) {
        const ulonglong2* wr = (const ulonglong2*)(cW1 + o * 64 + c0);  // const port
        ull h2a = pack2(0.f, 0.f), h2b = pack2(0.f, 0.f);
        #pragma unroll
        for (int q = 0; q < 8; q++) {
            ulonglong2 v = wr[q];
            h2a = fma2(v.x, E2[2*q],   h2a);
            h2b = fma2(v.y, E2[2*q+1], h2b);
        }
        float a0, a1, b0, b1v;
        unpack2(h2a, a0, a1);
        unpack2(h2b, b0, b1v);
        float hp = (a0 + a1) + (b0 + b1v);
        hp += __shfl_xor_sync(0xffffffffu, hp, 16);   // combine channel halves
        float hh = fmaxf(hp + cB1[o], 0.f);
        ull hh2 = pack2(hh, hh);

        const ulonglong2* wc = (const ulonglong2*)(sW2t + o * 64 + c0);  // smem
        #pragma unroll
        for (int q = 0; q < 8; q++) {
            ulonglong2 v = wc[q];
            acc2[2*q]   = fma2(v.x, hh2, acc2[2*q]);
            acc2[2*q+1] = fma2(v.y, hh2, acc2[2*q+1]);
        }
    }

    float* O = out + (size_t)b * CC * HWSZ + (size_t)c0 * HWSZ + p;
    #pragma unroll
    for (int q = 0; q < 16; q++) {
        float lo, hi;
        unpack2(acc2[q], lo, hi);
        O[(size_t)(2*q)   * HWSZ] = lo;
        O[(size_t)(2*q+1) * HWSZ] = hi;
    }
}

extern "C" void kernel_launch(void* const* d_in, const int* in_sizes, int n_in,
                              void* d_out, int out_size) {
    const float* x  = (const float*)d_in[0];
    const float* gw = (const float*)d_in[1];
    const float* gb = (const float*)d_in[2];
    const float* w1 = (const float*)d_in[3];
    const float* b1 = (const float*)d_in[4];
    const float* w2 = (const float*)d_in[5];
    const float* b2 = (const float*)d_in[6];
    float* out = (float*)d_out;

    cudaMemcpyToSymbolAsync(cW1, w1, 128*64*sizeof(float), 0, cudaMemcpyDeviceToDevice);
    cudaMemcpyToSymbolAsync(cB1, b1, 128*sizeof(float),    0, cudaMemcpyDeviceToDevice);
    cudaMemcpyToSymbolAsync(cB2, b2, 64*sizeof(float),     0, cudaMemcpyDeviceToDevice);

    k_init<<<1, 256>>>();
    k_down<<<BB*CC*2, 256>>>(x);
    k_df<<<dim3(HWSZ/256, BB), 256>>>(x);

    size_t smem = (size_t)(8192 + 64 + 64) * sizeof(float);
    cudaFuncSetAttribute(k_mainffn, cudaFuncAttributeMaxDynamicSharedMemorySize, (int)smem);
    k_mainffn<<<(BB*HWSZ) / 64, 128, smem>>>(x, gw, gb, w2, out);
}

// round 6
// speedup vs baseline: 2.2470x; 2.2470x over previous
#include <cuda_runtime.h>

#define BB 4
#define CC 64
#define HH 192
#define WWI 192
#define HWSZ (HH*WWI)
#define HD 96
#define WD 96

// ---- scratch (static device globals; no runtime allocation) ----
__device__ float g_down[BB*CC*HD*WD];          // 9.4 MB
__device__ float g_df[BB*HWSZ];
__device__ float g_nsq[BB*HWSZ];
__device__ unsigned g_dfmin[BB];
__device__ unsigned g_dfmax[BB];
__device__ float g_sum[BB*CC];
__device__ float g_ssq[BB*CC];
__device__ float g_enh[(size_t)BB*CC*HWSZ];    // 37.7 MB

typedef unsigned long long ull;

__device__ __forceinline__ ull pack2(float lo, float hi) {
    ull r; asm("mov.b64 %0, {%1, %2};" : "=l"(r) : "f"(lo), "f"(hi)); return r;
}
__device__ __forceinline__ void unpack2(ull v, float& lo, float& hi) {
    asm("mov.b64 {%0, %1}, %2;" : "=f"(lo), "=f"(hi) : "l"(v));
}
__device__ __forceinline__ ull fma2(ull a, ull b, ull c) {
    ull d; asm("fma.rn.f32x2 %0, %1, %2, %3;" : "=l"(d) : "l"(a), "l"(b), "l"(c)); return d;
}

__global__ void k_init() {
    int t = blockIdx.x * 256 + threadIdx.x;
    if (t < BB) { g_dfmin[t] = 0x7f800000u; g_dfmax[t] = 0u; }
    if (t < BB*CC) { g_sum[t] = 0.f; g_ssq[t] = 0.f; }
}

// 0.5x bilinear == 2x2 average pooling; also accumulates GroupNorm sum/sumsq.
__global__ void k_down(const float* __restrict__ x) {
    int blk  = blockIdx.x;
    int bc   = blk >> 1;
    int half = blk & 1;
    const float* xp = x + (size_t)bc * HWSZ;
    float* dp = g_down + (size_t)bc * (HD*WD);

    float s = 0.f, q = 0.f;
    for (int idx = threadIdx.x; idx < 48*48; idx += 256) {
        int jp = idx % 48;
        int r  = idx / 48;
        int ii = half * 48 + r;
        const float4 v0 = *(const float4*)(xp + (2*ii)   * WWI + 4*jp);
        const float4 v1 = *(const float4*)(xp + (2*ii+1) * WWI + 4*jp);
        float o0 = 0.5f*(0.5f*v0.x + 0.5f*v1.x) + 0.5f*(0.5f*v0.y + 0.5f*v1.y);
        float o1 = 0.5f*(0.5f*v0.z + 0.5f*v1.z) + 0.5f*(0.5f*v0.w + 0.5f*v1.w);
        dp[ii*WD + 2*jp]   = o0;
        dp[ii*WD + 2*jp+1] = o1;
        s += ((v0.x+v0.y)+(v0.z+v0.w)) + ((v1.x+v1.y)+(v1.z+v1.w));
        q += ((v0.x*v0.x+v0.y*v0.y)+(v0.z*v0.z+v0.w*v0.w))
           + ((v1.x*v1.x+v1.y*v1.y)+(v1.z*v1.z+v1.w*v1.w));
    }
    __shared__ float ss[256], sq[256];
    ss[threadIdx.x] = s; sq[threadIdx.x] = q;
    __syncthreads();
    for (int st = 128; st > 0; st >>= 1) {
        if (threadIdx.x < st) {
            ss[threadIdx.x] += ss[threadIdx.x+st];
            sq[threadIdx.x] += sq[threadIdx.x+st];
        }
        __syncthreads();
    }
    if (threadIdx.x == 0) {
        atomicAdd(&g_sum[bc], ss[0]);
        atomicAdd(&g_ssq[bc], sq[0]);
    }
}

// df map (sum_c |x - up(down(x))|), per-pixel normsq over C, per-batch min/max
__global__ void k_df(const float* __restrict__ x) {
    int p = blockIdx.x * 256 + threadIdx.x;
    int b = blockIdx.y;
    int h = p / WWI, w = p % WWI;

    float sh = fminf(fmaxf((h + 0.5f) * 0.5f - 0.5f, 0.f), (float)(HD-1));
    float sw = fminf(fmaxf((w + 0.5f) * 0.5f - 0.5f, 0.f), (float)(WD-1));
    int hl = (int)sh; int hh2 = min(hl+1, HD-1); float wh = sh - (float)hl;
    int wl = (int)sw; int wh2 = min(wl+1, WD-1); float ww = sw - (float)wl;
    int i00 = hl*WD+wl, i10 = hh2*WD+wl, i01 = hl*WD+wh2, i11 = hh2*WD+wh2;

    const float* xb = x + (size_t)b * CC * HWSZ + p;
    const float* db = g_down + (size_t)b * CC * HD * WD;

    float df = 0.f, nsq = 0.f;
    #pragma unroll 8
    for (int c = 0; c < CC; c++) {
        float xv = xb[(size_t)c * HWSZ];
        const float* dc = db + c * HD * WD;
        float u0  = dc[i00]*(1.f-wh) + dc[i10]*wh;
        float u1  = dc[i01]*(1.f-wh) + dc[i11]*wh;
        float xdu = u0*(1.f-ww) + u1*ww;
        df  += fabsf(xv - xdu);
        nsq += xv * xv;
    }
    g_df[b*HWSZ+p]  = df;
    g_nsq[b*HWSZ+p] = nsq;

    __shared__ float smn[256], smx[256];
    int tid = threadIdx.x;
    smn[tid] = df; smx[tid] = df;
    __syncthreads();
    for (int s = 128; s > 0; s >>= 1) {
        if (tid < s) {
            smn[tid] = fminf(smn[tid], smn[tid+s]);
            smx[tid] = fmaxf(smx[tid], smx[tid+s]);
        }
        __syncthreads();
    }
    if (tid == 0) {
        atomicMin(&g_dfmin[b], __float_as_uint(smn[0]));
        atomicMax(&g_dfmax[b], __float_as_uint(smx[0]));
    }
}

// phase A: detail gating + cosine top-k aggregation + GroupNorm add -> g_enh
__global__ void k_main(const float* __restrict__ x,
                       const float* __restrict__ gw, const float* __restrict__ gb) {
    int p = blockIdx.x * 256 + threadIdx.x;
    int b = blockIdx.y;

    __shared__ float sA[CC], sB[CC];
    if (threadIdx.x < CC) {        // fold GN into per-(b,c) affine, per block
        int c = threadIdx.x, g = c >> 1;
        int base = b * CC + 2 * g;
        float n2  = 2.f * (float)HWSZ;
        float mu  = (g_sum[base] + g_sum[base+1]) / n2;
        float var = (g_ssq[base] + g_ssq[base+1]) / n2 - mu*mu;
        float inv = rsqrtf(var + 1e-5f);
        float A = gw[c] * inv;
        sA[c] = A;
        sB[c] = gb[c] - mu * A;
    }
    __syncthreads();

    int h = p / WWI, w = p % WWI;
    const float* xb = x + (size_t)b * CC * HWSZ + p;
    float* eb = g_enh + (size_t)b * CC * HWSZ + p;

    float dmin = __uint_as_float(g_dfmin[b]);
    float dmax = __uint_as_float(g_dfmax[b]);
    float df   = g_df[b*HWSZ + p];
    float t0   = (df - dmin) / ((dmax - dmin) + 1e-8f);
    float dfp  = t0 * t0;

    if (!(dfp > 0.3f)) {   // not processed: enhanced = x + (A*x+B)
        #pragma unroll 8
        for (int c = 0; c < CC; c++) {
            float xv = xb[(size_t)c * HWSZ];
            eb[(size_t)c * HWSZ] = xv + (sA[c]*xv + sB[c]);
        }
        return;
    }

    int kk = min(1 + (int)rintf(dfp * 15.f), 9);

    bool val[9];
    int  doff[9];
    #pragma unroll
    for (int j = 0; j < 9; j++) {
        int dy = j/3 - 1, dx = j - 3*(j/3) - 1;
        val[j]  = ((unsigned)(h+dy) < HH) && ((unsigned)(w+dx) < WWI);
        doff[j] = dy * WWI + dx;
    }

    float dot[9];
    #pragma unroll
    for (int j = 0; j < 9; j++) dot[j] = 0.f;

    #pragma unroll 4
    for (int c = 0; c < CC; c++) {
        const float* rc = xb + (size_t)c * HWSZ;
        float xv = rc[0];
        #pragma unroll
        for (int j = 0; j < 9; j++)
            if (val[j]) dot[j] = fmaf(xv, rc[doff[j]], dot[j]);
    }

    float ncen = fmaxf(sqrtf(g_nsq[b*HWSZ + p]), 1e-12f);
    float sim[9];
    #pragma unroll
    for (int j = 0; j < 9; j++) {
        if (val[j]) {
            float nn = fmaxf(sqrtf(g_nsq[b*HWSZ + p + doff[j]]), 1e-12f);
            sim[j] = dot[j] / (ncen * nn);
        } else {
            sim[j] = 0.f;
        }
    }

    // stable top-k via rank (== stable argsort of -sim), in registers
    float wt[9];
    float wsum = 0.f;
    #pragma unroll
    for (int j = 0; j < 9; j++) {
        int rank = 0;
        #pragma unroll
        for (int l = 0; l < 9; l++) {
            if (l != j) {
                bool beats = (sim[l] > sim[j]) || (sim[l] == sim[j] && l < j);
                rank += beats ? 1 : 0;
            }
        }
        float wv = (rank < kk) ? expf(sim[j]) : 0.f;
        wt[j] = wv;
        wsum += wv;
    }
    float invw = 1.f / fmaxf(wsum, 1e-12f);
    #pragma unroll
    for (int j = 0; j < 9; j++) wt[j] *= invw;

    #pragma unroll 4
    for (int c = 0; c < CC; c++) {
        const float* rc = xb + (size_t)c * HWSZ;
        float acc = 0.f;
        #pragma unroll
        for (int j = 0; j < 9; j++)
            if (val[j]) acc = fmaf(wt[j], rc[doff[j]], acc);
        float xv = rc[0];
        eb[(size_t)c * HWSZ] = acc + (sA[c]*xv + sB[c]);
    }
}

// ---------------- register-tiled FFN GEMM ----------------
// out = E + W2 @ relu(W1 @ E + b1) + b2, E = g_enh, per-block tile of 64 pixels.
// smem: sE[64c][64px] 16KB | sW1t[64c][128o] 32KB | sW2t[128o][64c] 32KB |
//       sH[128o][64px] 32KB | sb1[128] | sb2[64]
#define SM_E    0
#define SM_W1T  4096
#define SM_W2T  (4096+8192)
#define SM_H    (4096+8192+8192)
#define SM_B1   (4096+8192+8192+8192)
#define SM_B2   (SM_B1+128)
#define SM_TOT  (SM_B2+64)

__global__ void __launch_bounds__(256, 2) k_ffn(
    const float* __restrict__ w1, const float* __restrict__ b1,
    const float* __restrict__ w2, const float* __restrict__ b2,
    float* __restrict__ out)
{
    extern __shared__ float sm[];
    int tid = threadIdx.x;

    long long P0 = (long long)blockIdx.x * 64;     // global pixel base
    int b  = (int)(P0 / HWSZ);
    int p0 = (int)(P0 - (long long)b * HWSZ);
    const float* E = g_enh + (size_t)b * CC * HWSZ + p0;

    // stage smem
    for (int i = tid; i < 8192; i += 256) {        // sW1t[c][o] = w1[o][c]
        int c = i >> 7, o = i & 127;
        sm[SM_W1T + i] = w1[o * 64 + c];
    }
    for (int i = tid; i < 8192; i += 256) {        // sW2t[o][c] = w2[c][o]
        int o = i >> 6, c = i & 63;
        sm[SM_W2T + i] = w2[c * 128 + o];
    }
    {   // sE[c][px]: 4096 floats, coalesced float4 loads
        int q = tid;                               // 0..255 -> (c, px4)
        #pragma unroll
        for (int r = 0; r < 4; r++) {
            int c   = (q + r*256) >> 4;
            int px4 = (q + r*256) & 15;
            float4 v = *(const float4*)(E + (size_t)c * HWSZ + px4*4);
            *(float4*)(sm + SM_E + c*64 + px4*4) = v;
        }
    }
    if (tid < 128) sm[SM_B1 + tid] = b1[tid];
    if (tid < 64)  sm[SM_B2 + tid] = b2[tid];
    __syncthreads();

    // ---- GEMM1: H[128o][64px] = relu(W1 @ E + b1), thread tile 8o x 4px ----
    int og = tid >> 4;           // 0..15 -> o_base = og*8
    int pg = tid & 15;           // 0..15 -> px_base = pg*4
    int ob = og * 8, pb = pg * 4;

    ull acc1[4][4];              // [o-pair][px]
    #pragma unroll
    for (int i = 0; i < 4; i++)
        #pragma unroll
        for (int j = 0; j < 4; j++) acc1[i][j] = 0ull;

    #pragma unroll 4
    for (int c = 0; c < 64; c++) {
        const ulonglong2* wp = (const ulonglong2*)(sm + SM_W1T + c*128 + ob);
        ulonglong2 wA = wp[0], wB = wp[1];          // 8 o-weights as 4 pairs
        float4 ev = *(const float4*)(sm + SM_E + c*64 + pb);
        ull e0 = pack2(ev.x, ev.x), e1 = pack2(ev.y, ev.y);
        ull e2 = pack2(ev.z, ev.z), e3 = pack2(ev.w, ev.w);
        acc1[0][0] = fma2(wA.x, e0, acc1[0][0]);
        acc1[0][1] = fma2(wA.x, e1, acc1[0][1]);
        acc1[0][2] = fma2(wA.x, e2, acc1[0][2]);
        acc1[0][3] = fma2(wA.x, e3, acc1[0][3]);
        acc1[1][0] = fma2(wA.y, e0, acc1[1][0]);
        acc1[1][1] = fma2(wA.y, e1, acc1[1][1]);
        acc1[1][2] = fma2(wA.y, e2, acc1[1][2]);
        acc1[1][3] = fma2(wA.y, e3, acc1[1][3]);
        acc1[2][0] = fma2(wB.x, e0, acc1[2][0]);
        acc1[2][1] = fma2(wB.x, e1, acc1[2][1]);
        acc1[2][2] = fma2(wB.x, e2, acc1[2][2]);
        acc1[2][3] = fma2(wB.x, e3, acc1[2][3]);
        acc1[3][0] = fma2(wB.y, e0, acc1[3][0]);
        acc1[3][1] = fma2(wB.y, e1, acc1[3][1]);
        acc1[3][2] = fma2(wB.y, e2, acc1[3][2]);
        acc1[3][3] = fma2(wB.y, e3, acc1[3][3]);
    }

    __syncthreads();   // everyone done reading sE/sW1t before H writes (H is its own region, but keep phases clean)

    #pragma unroll
    for (int i = 0; i < 4; i++) {
        float lo0, hi0, lo1, hi1, lo2, hi2, lo3, hi3;
        unpack2(acc1[i][0], lo0, hi0);
        unpack2(acc1[i][1], lo1, hi1);
        unpack2(acc1[i][2], lo2, hi2);
        unpack2(acc1[i][3], lo3, hi3);
        int oo = ob + 2*i;
        float bl = sm[SM_B1 + oo], bh = sm[SM_B1 + oo + 1];
        float4 rl = { fmaxf(lo0+bl,0.f), fmaxf(lo1+bl,0.f), fmaxf(lo2+bl,0.f), fmaxf(lo3+bl,0.f) };
        float4 rh = { fmaxf(hi0+bh,0.f), fmaxf(hi1+bh,0.f), fmaxf(hi2+bh,0.f), fmaxf(hi3+bh,0.f) };
        *(float4*)(sm + SM_H + (oo)   * 64 + pb) = rl;
        *(float4*)(sm + SM_H + (oo+1) * 64 + pb) = rh;
    }
    __syncthreads();

    // ---- GEMM2: OUT[64c][64px] = E + W2 @ H + b2, thread tile 4c x 4px ----
    int cg = tid >> 4;           // 0..15 -> c_base = cg*4
    int cb = cg * 4;

    ull acc2[2][4];              // [c-pair][px], init = e + b2
    #pragma unroll
    for (int i = 0; i < 2; i++) {
        int c = cb + 2*i;
        float b2l = sm[SM_B2 + c], b2h = sm[SM_B2 + c + 1];
        const float* el = sm + SM_E + c*64 + pb;
        const float* eh = sm + SM_E + (c+1)*64 + pb;
        #pragma unroll
        for (int j = 0; j < 4; j++)
            acc2[i][j] = pack2(el[j] + b2l, eh[j] + b2h);
    }

    #pragma unroll 4
    for (int o = 0; o < 128; o++) {
        ulonglong2 wv = *(const ulonglong2*)(sm + SM_W2T + o*64 + cb);  // 4 c-weights
        float4 hv = *(const float4*)(sm + SM_H + o*64 + pb);
        ull h0 = pack2(hv.x, hv.x), h1 = pack2(hv.y, hv.y);
        ull h2 = pack2(hv.z, hv.z), h3 = pack2(hv.w, hv.w);
        acc2[0][0] = fma2(wv.x, h0, acc2[0][0]);
        acc2[0][1] = fma2(wv.x, h1, acc2[0][1]);
        acc2[0][2] = fma2(wv.x, h2, acc2[0][2]);
        acc2[0][3] = fma2(wv.x, h3, acc2[0][3]);
        acc2[1][0] = fma2(wv.y, h0, acc2[1][0]);
        acc2[1][1] = fma2(wv.y, h1, acc2[1][1]);
        acc2[1][2] = fma2(wv.y, h2, acc2[1][2]);
        acc2[1][3] = fma2(wv.y, h3, acc2[1][3]);
    }

    float* O = out + (size_t)b * CC * HWSZ + p0;
    #pragma unroll
    for (int i = 0; i < 2; i++) {
        float lo0, hi0, lo1, hi1, lo2, hi2, lo3, hi3;
        unpack2(acc2[i][0], lo0, hi0);
        unpack2(acc2[i][1], lo1, hi1);
        unpack2(acc2[i][2], lo2, hi2);
        unpack2(acc2[i][3], lo3, hi3);
        int c = cb + 2*i;
        float4 vl = { lo0, lo1, lo2, lo3 };
        float4 vh = { hi0, hi1, hi2, hi3 };
        *(float4*)(O + (size_t)c     * HWSZ + pb) = vl;
        *(float4*)(O + (size_t)(c+1) * HWSZ + pb) = vh;
    }
}

extern "C" void kernel_launch(void* const* d_in, const int* in_sizes, int n_in,
                              void* d_out, int out_size) {
    const float* x  = (const float*)d_in[0];
    const float* gw = (const float*)d_in[1];
    const float* gb = (const float*)d_in[2];
    const float* w1 = (const float*)d_in[3];
    const float* b1 = (const float*)d_in[4];
    const float* w2 = (const float*)d_in[5];
    const float* b2 = (const float*)d_in[6];
    float* out = (float*)d_out;

    k_init<<<1, 256>>>();
    k_down<<<BB*CC*2, 256>>>(x);
    k_df<<<dim3(HWSZ/256, BB), 256>>>(x);
    k_main<<<dim3(HWSZ/256, BB), 256>>>(x, gw, gb);

    size_t smem = (size_t)SM_TOT * sizeof(float);
    cudaFuncSetAttribute(k_ffn, cudaFuncAttributeMaxDynamicSharedMemorySize, (int)smem);
    k_ffn<<<(BB*HWSZ) / 64, 256, smem>>>(w1, b1, w2, b2, out);
}

// round 7
// speedup vs baseline: 3.4418x; 1.5318x over previous
#include <cuda_runtime.h>

#define BB 4
#define CC 64
#define HH 192
#define WWI 192
#define HWSZ (HH*WWI)
#define HD 96
#define WD 96

// ---- scratch (static device globals; no runtime allocation) ----
__device__ float g_down[BB*CC*HD*WD];          // 9.4 MB
__device__ float g_df[BB*HWSZ];
__device__ float g_nsq[BB*HWSZ];
__device__ unsigned g_dfmin[BB];
__device__ unsigned g_dfmax[BB];
__device__ float g_sum[BB*CC];
__device__ float g_ssq[BB*CC];
__device__ float g_enh[(size_t)BB*CC*HWSZ];    // 37.7 MB

typedef unsigned long long ull;

__device__ __forceinline__ ull pack2(float lo, float hi) {
    ull r; asm("mov.b64 %0, {%1, %2};" : "=l"(r) : "f"(lo), "f"(hi)); return r;
}
__device__ __forceinline__ void unpack2(ull v, float& lo, float& hi) {
    asm("mov.b64 {%0, %1}, %2;" : "=f"(lo), "=f"(hi) : "l"(v));
}
__device__ __forceinline__ ull fma2(ull a, ull b, ull c) {
    ull d; asm("fma.rn.f32x2 %0, %1, %2, %3;" : "=l"(d) : "l"(a), "l"(b), "l"(c)); return d;
}

__global__ void k_init() {
    int t = blockIdx.x * 256 + threadIdx.x;
    if (t < BB) { g_dfmin[t] = 0x7f800000u; g_dfmax[t] = 0u; }
    if (t < BB*CC) { g_sum[t] = 0.f; g_ssq[t] = 0.f; }
}

// 0.5x bilinear == 2x2 average pooling; also accumulates GroupNorm sum/sumsq.
__global__ void k_down(const float* __restrict__ x) {
    int blk  = blockIdx.x;
    int bc   = blk >> 1;
    int half = blk & 1;
    const float* xp = x + (size_t)bc * HWSZ;
    float* dp = g_down + (size_t)bc * (HD*WD);

    float s = 0.f, q = 0.f;
    for (int idx = threadIdx.x; idx < 48*48; idx += 256) {
        int jp = idx % 48;
        int r  = idx / 48;
        int ii = half * 48 + r;
        const float4 v0 = *(const float4*)(xp + (2*ii)   * WWI + 4*jp);
        const float4 v1 = *(const float4*)(xp + (2*ii+1) * WWI + 4*jp);
        float o0 = 0.5f*(0.5f*v0.x + 0.5f*v1.x) + 0.5f*(0.5f*v0.y + 0.5f*v1.y);
        float o1 = 0.5f*(0.5f*v0.z + 0.5f*v1.z) + 0.5f*(0.5f*v0.w + 0.5f*v1.w);
        dp[ii*WD + 2*jp]   = o0;
        dp[ii*WD + 2*jp+1] = o1;
        s += ((v0.x+v0.y)+(v0.z+v0.w)) + ((v1.x+v1.y)+(v1.z+v1.w));
        q += ((v0.x*v0.x+v0.y*v0.y)+(v0.z*v0.z+v0.w*v0.w))
           + ((v1.x*v1.x+v1.y*v1.y)+(v1.z*v1.z+v1.w*v1.w));
    }
    __shared__ float ss[256], sq[256];
    ss[threadIdx.x] = s; sq[threadIdx.x] = q;
    __syncthreads();
    for (int st = 128; st > 0; st >>= 1) {
        if (threadIdx.x < st) {
            ss[threadIdx.x] += ss[threadIdx.x+st];
            sq[threadIdx.x] += sq[threadIdx.x+st];
        }
        __syncthreads();
    }
    if (threadIdx.x == 0) {
        atomicAdd(&g_sum[bc], ss[0]);
        atomicAdd(&g_ssq[bc], sq[0]);
    }
}

// df map (sum_c |x - up(down(x))|), per-pixel normsq over C, per-batch min/max
__global__ void k_df(const float* __restrict__ x) {
    int p = blockIdx.x * 256 + threadIdx.x;
    int b = blockIdx.y;
    int h = p / WWI, w = p % WWI;

    float sh = fminf(fmaxf((h + 0.5f) * 0.5f - 0.5f, 0.f), (float)(HD-1));
    float sw = fminf(fmaxf((w + 0.5f) * 0.5f - 0.5f, 0.f), (float)(WD-1));
    int hl = (int)sh; int hh2 = min(hl+1, HD-1); float wh = sh - (float)hl;
    int wl = (int)sw; int wh2 = min(wl+1, WD-1); float ww = sw - (float)wl;
    int i00 = hl*WD+wl, i10 = hh2*WD+wl, i01 = hl*WD+wh2, i11 = hh2*WD+wh2;

    const float* xb = x + (size_t)b * CC * HWSZ + p;
    const float* db = g_down + (size_t)b * CC * HD * WD;

    float df = 0.f, nsq = 0.f;
    #pragma unroll 8
    for (int c = 0; c < CC; c++) {
        float xv = xb[(size_t)c * HWSZ];
        const float* dc = db + c * HD * WD;
        float u0  = dc[i00]*(1.f-wh) + dc[i10]*wh;
        float u1  = dc[i01]*(1.f-wh) + dc[i11]*wh;
        float xdu = u0*(1.f-ww) + u1*ww;
        df  += fabsf(xv - xdu);
        nsq += xv * xv;
    }
    g_df[b*HWSZ+p]  = df;
    g_nsq[b*HWSZ+p] = nsq;

    __shared__ float smn[256], smx[256];
    int tid = threadIdx.x;
    smn[tid] = df; smx[tid] = df;
    __syncthreads();
    for (int s = 128; s > 0; s >>= 1) {
        if (tid < s) {
            smn[tid] = fminf(smn[tid], smn[tid+s]);
            smx[tid] = fmaxf(smx[tid], smx[tid+s]);
        }
        __syncthreads();
    }
    if (tid == 0) {
        atomicMin(&g_dfmin[b], __float_as_uint(smn[0]));
        atomicMax(&g_dfmax[b], __float_as_uint(smx[0]));
    }
}

// phase A: detail gating + cosine top-k aggregation + GroupNorm add -> g_enh
__global__ void k_main(const float* __restrict__ x,
                       const float* __restrict__ gw, const float* __restrict__ gb) {
    int p = blockIdx.x * 256 + threadIdx.x;
    int b = blockIdx.y;

    __shared__ float sA[CC], sB[CC];
    if (threadIdx.x < CC) {        // fold GN into per-(b,c) affine, per block
        int c = threadIdx.x, g = c >> 1;
        int base = b * CC + 2 * g;
        float n2  = 2.f * (float)HWSZ;
        float mu  = (g_sum[base] + g_sum[base+1]) / n2;
        float var = (g_ssq[base] + g_ssq[base+1]) / n2 - mu*mu;
        float inv = rsqrtf(var + 1e-5f);
        float A = gw[c] * inv;
        sA[c] = A;
        sB[c] = gb[c] - mu * A;
    }
    __syncthreads();

    int h = p / WWI, w = p % WWI;
    const float* xb = x + (size_t)b * CC * HWSZ + p;
    float* eb = g_enh + (size_t)b * CC * HWSZ + p;

    float dmin = __uint_as_float(g_dfmin[b]);
    float dmax = __uint_as_float(g_dfmax[b]);
    float df   = g_df[b*HWSZ + p];
    float t0   = (df - dmin) / ((dmax - dmin) + 1e-8f);
    float dfp  = t0 * t0;

    if (!(dfp > 0.3f)) {   // not processed: enhanced = x + (A*x+B)
        #pragma unroll 8
        for (int c = 0; c < CC; c++) {
            float xv = xb[(size_t)c * HWSZ];
            eb[(size_t)c * HWSZ] = xv + (sA[c]*xv + sB[c]);
        }
        return;
    }

    int kk = min(1 + (int)rintf(dfp * 15.f), 9);

    bool val[9];
    int  doff[9];
    #pragma unroll
    for (int j = 0; j < 9; j++) {
        int dy = j/3 - 1, dx = j - 3*(j/3) - 1;
        val[j]  = ((unsigned)(h+dy) < HH) && ((unsigned)(w+dx) < WWI);
        doff[j] = dy * WWI + dx;
    }

    float dot[9];
    #pragma unroll
    for (int j = 0; j < 9; j++) dot[j] = 0.f;

    #pragma unroll 4
    for (int c = 0; c < CC; c++) {
        const float* rc = xb + (size_t)c * HWSZ;
        float xv = rc[0];
        #pragma unroll
        for (int j = 0; j < 9; j++)
            if (val[j]) dot[j] = fmaf(xv, rc[doff[j]], dot[j]);
    }

    float ncen = fmaxf(sqrtf(g_nsq[b*HWSZ + p]), 1e-12f);
    float sim[9];
    #pragma unroll
    for (int j = 0; j < 9; j++) {
        if (val[j]) {
            float nn = fmaxf(sqrtf(g_nsq[b*HWSZ + p + doff[j]]), 1e-12f);
            sim[j] = dot[j] / (ncen * nn);
        } else {
            sim[j] = 0.f;
        }
    }

    // stable top-k via rank (== stable argsort of -sim), in registers
    float wt[9];
    float wsum = 0.f;
    #pragma unroll
    for (int j = 0; j < 9; j++) {
        int rank = 0;
        #pragma unroll
        for (int l = 0; l < 9; l++) {
            if (l != j) {
                bool beats = (sim[l] > sim[j]) || (sim[l] == sim[j] && l < j);
                rank += beats ? 1 : 0;
            }
        }
        float wv = (rank < kk) ? expf(sim[j]) : 0.f;
        wt[j] = wv;
        wsum += wv;
    }
    float invw = 1.f / fmaxf(wsum, 1e-12f);
    #pragma unroll
    for (int j = 0; j < 9; j++) wt[j] *= invw;

    #pragma unroll 4
    for (int c = 0; c < CC; c++) {
        const float* rc = xb + (size_t)c * HWSZ;
        float acc = 0.f;
        #pragma unroll
        for (int j = 0; j < 9; j++)
            if (val[j]) acc = fmaf(wt[j], rc[doff[j]], acc);
        float xv = rc[0];
        eb[(size_t)c * HWSZ] = acc + (sA[c]*xv + sB[c]);
    }
}

// ---------------- persistent register-tiled FFN GEMM ----------------
// out = E + W2 @ relu(W1 @ E + b1) + b2. Weights staged ONCE per resident CTA;
// each CTA loops over 64-pixel tiles.
// smem: sE[64c][64px] 16KB | sW1t[64c][128o] 32KB | sW2t[128o][64c] 32KB |
//       sH[128o][64px] 32KB | sb1[128] | sb2[64]
#define SM_E    0
#define SM_W1T  4096
#define SM_W2T  (4096+8192)
#define SM_H    (4096+8192+8192)
#define SM_B1   (4096+8192+8192+8192)
#define SM_B2   (SM_B1+128)
#define SM_TOT  (SM_B2+64)
#define NTILES  ((BB*HWSZ)/64)     // 2304

__global__ void __launch_bounds__(256, 2) k_ffn(
    const float* __restrict__ w1, const float* __restrict__ b1,
    const float* __restrict__ w2, const float* __restrict__ b2,
    float* __restrict__ out)
{
    extern __shared__ float sm[];
    int tid = threadIdx.x;

    // ---- one-time weight staging ----
    for (int i = tid; i < 8192; i += 256) {        // sW1t[c][o] = w1[o][c]
        int c = i >> 7, o = i & 127;
        sm[SM_W1T + i] = w1[o * 64 + c];
    }
    for (int i = tid; i < 8192; i += 256) {        // sW2t[o][c] = w2[c][o]
        int o = i >> 6, c = i & 63;
        sm[SM_W2T + i] = w2[c * 128 + o];
    }
    if (tid < 128) sm[SM_B1 + tid] = b1[tid];
    if (tid < 64)  sm[SM_B2 + tid] = b2[tid];

    int og = tid >> 4;           // 0..15
    int pg = tid & 15;           // 0..15
    int ob = og * 8, pb = pg * 4;
    int cb = og * 4;             // GEMM2 c-base (same decomposition)

    for (int tile = blockIdx.x; tile < NTILES; tile += gridDim.x) {
        long long P0 = (long long)tile * 64;
        int b  = (int)(P0 / HWSZ);
        int p0 = (int)(P0 - (long long)b * HWSZ);
        const float* E = g_enh + (size_t)b * CC * HWSZ + p0;

        __syncthreads();    // prev iter fully done with sE / sH
        {   // sE[c][px]: coalesced float4 loads
            #pragma unroll
            for (int r = 0; r < 4; r++) {
                int c   = (tid + r*256) >> 4;
                int px4 = (tid + r*256) & 15;
                float4 v = *(const float4*)(E + (size_t)c * HWSZ + px4*4);
                *(float4*)(sm + SM_E + c*64 + px4*4) = v;
            }
        }
        __syncthreads();

        // ---- GEMM1: H = relu(W1 @ E + b1), thread tile 8o x 4px ----
        ull acc1[4][4];
        #pragma unroll
        for (int i = 0; i < 4; i++)
            #pragma unroll
            for (int j = 0; j < 4; j++) acc1[i][j] = 0ull;

        #pragma unroll 4
        for (int c = 0; c < 64; c++) {
            const ulonglong2* wp = (const ulonglong2*)(sm + SM_W1T + c*128 + ob);
            ulonglong2 wA = wp[0], wB = wp[1];
            float4 ev = *(const float4*)(sm + SM_E + c*64 + pb);
            ull e0 = pack2(ev.x, ev.x), e1 = pack2(ev.y, ev.y);
            ull e2 = pack2(ev.z, ev.z), e3 = pack2(ev.w, ev.w);
            acc1[0][0] = fma2(wA.x, e0, acc1[0][0]);
            acc1[0][1] = fma2(wA.x, e1, acc1[0][1]);
            acc1[0][2] = fma2(wA.x, e2, acc1[0][2]);
            acc1[0][3] = fma2(wA.x, e3, acc1[0][3]);
            acc1[1][0] = fma2(wA.y, e0, acc1[1][0]);
            acc1[1][1] = fma2(wA.y, e1, acc1[1][1]);
            acc1[1][2] = fma2(wA.y, e2, acc1[1][2]);
            acc1[1][3] = fma2(wA.y, e3, acc1[1][3]);
            acc1[2][0] = fma2(wB.x, e0, acc1[2][0]);
            acc1[2][1] = fma2(wB.x, e1, acc1[2][1]);
            acc1[2][2] = fma2(wB.x, e2, acc1[2][2]);
            acc1[2][3] = fma2(wB.x, e3, acc1[2][3]);
            acc1[3][0] = fma2(wB.y, e0, acc1[3][0]);
            acc1[3][1] = fma2(wB.y, e1, acc1[3][1]);
            acc1[3][2] = fma2(wB.y, e2, acc1[3][2]);
            acc1[3][3] = fma2(wB.y, e3, acc1[3][3]);
        }

        #pragma unroll
        for (int i = 0; i < 4; i++) {
            float lo0, hi0, lo1, hi1, lo2, hi2, lo3, hi3;
            unpack2(acc1[i][0], lo0, hi0);
            unpack2(acc1[i][1], lo1, hi1);
            unpack2(acc1[i][2], lo2, hi2);
            unpack2(acc1[i][3], lo3, hi3);
            int oo = ob + 2*i;
            float bl = sm[SM_B1 + oo], bh = sm[SM_B1 + oo + 1];
            float4 rl = { fmaxf(lo0+bl,0.f), fmaxf(lo1+bl,0.f), fmaxf(lo2+bl,0.f), fmaxf(lo3+bl,0.f) };
            float4 rh = { fmaxf(hi0+bh,0.f), fmaxf(hi1+bh,0.f), fmaxf(hi2+bh,0.f), fmaxf(hi3+bh,0.f) };
            *(float4*)(sm + SM_H + (oo)   * 64 + pb) = rl;
            *(float4*)(sm + SM_H + (oo+1) * 64 + pb) = rh;
        }
        __syncthreads();

        // ---- GEMM2: OUT = E + W2 @ H + b2, thread tile 4c x 4px ----
        ull acc2[2][4];
        #pragma unroll
        for (int i = 0; i < 2; i++) {
            int c = cb + 2*i;
            float b2l = sm[SM_B2 + c], b2h = sm[SM_B2 + c + 1];
            const float* el = sm + SM_E + c*64 + pb;
            const float* eh = sm + SM_E + (c+1)*64 + pb;
            #pragma unroll
            for (int j = 0; j < 4; j++)
                acc2[i][j] = pack2(el[j] + b2l, eh[j] + b2h);
        }

        #pragma unroll 4
        for (int o = 0; o < 128; o++) {
            ulonglong2 wv = *(const ulonglong2*)(sm + SM_W2T + o*64 + cb);
            float4 hv = *(const float4*)(sm + SM_H + o*64 + pb);
            ull h0 = pack2(hv.x, hv.x), h1 = pack2(hv.y, hv.y);
            ull h2 = pack2(hv.z, hv.z), h3 = pack2(hv.w, hv.w);
            acc2[0][0] = fma2(wv.x, h0, acc2[0][0]);
            acc2[0][1] = fma2(wv.x, h1, acc2[0][1]);
            acc2[0][2] = fma2(wv.x, h2, acc2[0][2]);
            acc2[0][3] = fma2(wv.x, h3, acc2[0][3]);
            acc2[1][0] = fma2(wv.y, h0, acc2[1][0]);
            acc2[1][1] = fma2(wv.y, h1, acc2[1][1]);
            acc2[1][2] = fma2(wv.y, h2, acc2[1][2]);
            acc2[1][3] = fma2(wv.y, h3, acc2[1][3]);
        }

        float* O = out + (size_t)b * CC * HWSZ + p0;
        #pragma unroll
        for (int i = 0; i < 2; i++) {
            float lo0, hi0, lo1, hi1, lo2, hi2, lo3, hi3;
            unpack2(acc2[i][0], lo0, hi0);
            unpack2(acc2[i][1], lo1, hi1);
            unpack2(acc2[i][2], lo2, hi2);
            unpack2(acc2[i][3], lo3, hi3);
            int c = cb + 2*i;
            float4 vl = { lo0, lo1, lo2, lo3 };
            float4 vh = { hi0, hi1, hi2, hi3 };
            *(float4*)(O + (size_t)c     * HWSZ + pb) = vl;
            *(float4*)(O + (size_t)(c+1) * HWSZ + pb) = vh;
        }
    }
}

extern "C" void kernel_launch(void* const* d_in, const int* in_sizes, int n_in,
                              void* d_out, int out_size) {
    const float* x  = (const float*)d_in[0];
    const float* gw = (const float*)d_in[1];
    const float* gb = (const float*)d_in[2];
    const float* w1 = (const float*)d_in[3];
    const float* b1 = (const float*)d_in[4];
    const float* w2 = (const float*)d_in[5];
    const float* b2 = (const float*)d_in[6];
    float* out = (float*)d_out;

    k_init<<<1, 256>>>();
    k_down<<<BB*CC*2, 256>>>(x);
    k_df<<<dim3(HWSZ/256, BB), 256>>>(x);
    k_main<<<dim3(HWSZ/256, BB), 256>>>(x, gw, gb);

    size_t smem = (size_t)SM_TOT * sizeof(float);
    cudaFuncSetAttribute(k_ffn, cudaFuncAttributeMaxDynamicSharedMemorySize, (int)smem);
    k_ffn<<<296, 256, smem>>>(w1, b1, w2, b2, out);
}